// round 4
// baseline (speedup 1.0000x reference)
#include <cuda_runtime.h>
#include <cstdint>

#define N_NODES 100000
#define IN_CH 128
#define HID 32
#define MAX_E 3400000

// ---- scratch: device globals. Referenced ONLY from device code. ----
__device__ __align__(16) float g_h[N_NODES * HID];    // h1, then reused as h2
__device__ __align__(16) float g_acc[N_NODES * HID];  // layer-1 accumulator
__device__ int   g_deg[N_NODES];
__device__ float g_dinv[N_NODES];
__device__ int   g_off[N_NODES + 1];
__device__ int   g_cursor[N_NODES];
__device__ int   g_csr_src[MAX_E];
__device__ int   g_src32[MAX_E];
__device__ int   g_dst32[MAX_E];
__device__ int   g_is64;

// ---------------- dtype probe: int64 edge_index has all-zero high words ----------------
__global__ void k_detect(const int* __restrict__ ei32, int E) {
    if (threadIdx.x == 0 && blockIdx.x == 0) {
        int all_zero_high = 1;
        int n = (E > 256) ? 256 : E;
        for (int i = 0; i < n; i++) {
            if (ei32[2 * i + 1] != 0) { all_zero_high = 0; break; }
        }
        g_is64 = all_zero_high;
    }
}

// ---------------- normalize edges to int32 ----------------
__global__ void k_convert(const void* __restrict__ ei, int E) {
    int e = blockIdx.x * blockDim.x + threadIdx.x;
    if (e >= E) return;
    if (g_is64) {
        const long long* p = (const long long*)ei;
        g_src32[e] = (int)p[e];
        g_dst32[e] = (int)p[e + E];
    } else {
        const int* p = (const int*)ei;
        g_src32[e] = p[e];
        g_dst32[e] = p[e + E];
    }
}

// ---------------- degree / dinv ----------------
__global__ void k_zero_deg(int n) {
    int i = blockIdx.x * blockDim.x + threadIdx.x;
    if (i < n) g_deg[i] = 0;
}

__global__ void k_deg(int E) {
    int e = blockIdx.x * blockDim.x + threadIdx.x;
    if (e < E) atomicAdd(&g_deg[g_dst32[e]], 1);
}

__global__ void k_dinv(int n) {
    int i = blockIdx.x * blockDim.x + threadIdx.x;
    if (i < n) g_dinv[i] = rsqrtf((float)g_deg[i] + 1.0f);  // +1 self-loop
}

// ---------------- CSR offsets (single-block scan) ----------------
__global__ void k_scan(int n) {
    __shared__ int s[1024];
    int t = threadIdx.x;
    int chunk = (n + 1023) / 1024;
    int b = t * chunk;
    int e = b + chunk; if (e > n) e = n;
    int sum = 0;
    for (int i = b; i < e; i++) sum += g_deg[i];
    s[t] = sum;
    __syncthreads();
    for (int d = 1; d < 1024; d <<= 1) {
        int v = (t >= d) ? s[t - d] : 0;
        __syncthreads();
        s[t] += v;
        __syncthreads();
    }
    int excl = (t == 0) ? 0 : s[t - 1];
    for (int i = b; i < e; i++) {
        int dv = g_deg[i];
        g_off[i] = excl;
        g_cursor[i] = excl;
        excl += dv;
    }
    if (t == 1023) g_off[n] = excl;
}

// ---------------- CSR fill ----------------
__global__ void k_fill(int E) {
    int e = blockIdx.x * blockDim.x + threadIdx.x;
    if (e >= E) return;
    int d = g_dst32[e];
    int pos = atomicAdd(&g_cursor[d], 1);
    g_csr_src[pos] = g_src32[e];
}

// ---------------- GEMM1: h1 = x @ W1 ; acc = b1 + h1*dinv^2 ----------------
__global__ void k_gemm1(const float* __restrict__ x,
                        const float* __restrict__ W1,
                        const float* __restrict__ b1, int n) {
    __shared__ __align__(16) float sW[IN_CH * HID];   // 16 KB
    __shared__ __align__(16) float xs[8 * IN_CH];     // 4 KB
    int tid = threadIdx.x;
    int nodeBase = blockIdx.x * 8;

    for (int i = tid; i < IN_CH * HID; i += 256) sW[i] = W1[i];

    {
        int nd = tid >> 5;
        int q = tid & 31;
        int node = nodeBase + nd;
        float4 v = make_float4(0.f, 0.f, 0.f, 0.f);
        if (node < n) v = ((const float4*)x)[(size_t)node * 32 + q];
        ((float4*)xs)[nd * 32 + q] = v;
    }
    __syncthreads();

    int nd = tid >> 5;
    int c = tid & 31;
    int node = nodeBase + nd;
    if (node >= n) return;

    const float4* xrow = ((const float4*)xs) + nd * 32;
    float a = 0.f;
#pragma unroll
    for (int k4 = 0; k4 < 32; k4++) {
        float4 xv = xrow[k4];
        a = fmaf(xv.x, sW[(k4 * 4 + 0) * HID + c], a);
        a = fmaf(xv.y, sW[(k4 * 4 + 1) * HID + c], a);
        a = fmaf(xv.z, sW[(k4 * 4 + 2) * HID + c], a);
        a = fmaf(xv.w, sW[(k4 * 4 + 3) * HID + c], a);
    }
    g_h[node * HID + c] = a;
    float di = g_dinv[node];
    g_acc[node * HID + c] = b1[c] + a * di * di;
}

// ---------------- GEMM2: h2 = relu(g_acc) @ W2 ; out = b2 + h2*dinv^2 ----------------
__global__ void k_gemm2(const float* __restrict__ W2,
                        const float* __restrict__ b2,
                        float* __restrict__ out, int n) {
    __shared__ __align__(16) float sW[HID * HID];
    __shared__ __align__(16) float as[8 * HID];
    int tid = threadIdx.x;
    int nodeBase = blockIdx.x * 8;

    for (int i = tid; i < HID * HID; i += 256) sW[i] = W2[i];

    {
        int nd = tid >> 5;
        int c = tid & 31;
        int node = nodeBase + nd;
        float v = 0.f;
        if (node < n) v = fmaxf(g_acc[(size_t)node * HID + c], 0.f);
        as[nd * HID + c] = v;
    }
    __syncthreads();

    int nd = tid >> 5;
    int c = tid & 31;
    int node = nodeBase + nd;
    if (node >= n) return;

    const float4* arow = ((const float4*)as) + nd * 8;
    float a = 0.f;
#pragma unroll
    for (int k4 = 0; k4 < 8; k4++) {
        float4 av = arow[k4];
        a = fmaf(av.x, sW[(k4 * 4 + 0) * HID + c], a);
        a = fmaf(av.y, sW[(k4 * 4 + 1) * HID + c], a);
        a = fmaf(av.z, sW[(k4 * 4 + 2) * HID + c], a);
        a = fmaf(av.w, sW[(k4 * 4 + 3) * HID + c], a);
    }
    g_h[node * HID + c] = a;  // h2
    float di = g_dinv[node];
    out[node * HID + c] = b2[c] + a * di * di;
}

// ---------------- aggregation: warp per node, 4 edge-slots x 8 float4-lanes ----
__device__ __forceinline__ void aggregate_node(float* __restrict__ outrow,
                                               int node, int lane) {
    int j = lane >> 3;  // edge slot 0..3
    int q = lane & 7;   // float4 index 0..7

    int beg = g_off[node];
    int end = g_off[node + 1];
    float dd = g_dinv[node];

    float4 acc = make_float4(0.f, 0.f, 0.f, 0.f);
    for (int i = beg + j; i < end; i += 4) {
        int s = g_csr_src[i];
        float w = g_dinv[s] * dd;
        const float4* vp = (const float4*)(g_h + (size_t)s * HID) + q;
        float4 v = *vp;
        acc.x = fmaf(v.x, w, acc.x);
        acc.y = fmaf(v.y, w, acc.y);
        acc.z = fmaf(v.z, w, acc.z);
        acc.w = fmaf(v.w, w, acc.w);
    }
#pragma unroll
    for (int m = 8; m <= 16; m <<= 1) {
        acc.x += __shfl_xor_sync(0xFFFFFFFFu, acc.x, m);
        acc.y += __shfl_xor_sync(0xFFFFFFFFu, acc.y, m);
        acc.z += __shfl_xor_sync(0xFFFFFFFFu, acc.z, m);
        acc.w += __shfl_xor_sync(0xFFFFFFFFu, acc.w, m);
    }
    if (j == 0) {
        float4* p = (float4*)outrow + q;
        float4 cur = *p;  // preinitialized (bias + self-loop)
        cur.x += acc.x; cur.y += acc.y; cur.z += acc.z; cur.w += acc.w;
        *p = cur;
    }
}

__global__ void k_aggregate1(int n) {
    int warp_id = (blockIdx.x * blockDim.x + threadIdx.x) >> 5;
    if (warp_id >= n) return;
    aggregate_node(g_acc + (size_t)warp_id * HID, warp_id, threadIdx.x & 31);
}

__global__ void k_aggregate2(float* __restrict__ out, int n) {
    int warp_id = (blockIdx.x * blockDim.x + threadIdx.x) >> 5;
    if (warp_id >= n) return;
    aggregate_node(out + (size_t)warp_id * HID, warp_id, threadIdx.x & 31);
}

extern "C" void kernel_launch(void* const* d_in, const int* in_sizes, int n_in,
                              void* d_out, int out_size) {
    const float* x  = (const float*)d_in[0];
    const void*  ei = d_in[1];
    const float* W1 = (const float*)d_in[2];
    const float* b1 = (const float*)d_in[3];
    const float* W2 = (const float*)d_in[4];
    const float* b2 = (const float*)d_in[5];
    float* out = (float*)d_out;

    const int N = in_sizes[0] / IN_CH;
    const int E = in_sizes[1] / 2;   // element count of edge_index = 2*E in either dtype

    // edge dtype probe + normalization to int32
    k_detect<<<1, 32>>>((const int*)ei, E);
    k_convert<<<(E + 255) / 256, 256>>>(ei, E);

    // degree + dinv
    k_zero_deg<<<(N + 255) / 256, 256>>>(N);
    k_deg<<<(E + 255) / 256, 256>>>(E);
    k_dinv<<<(N + 255) / 256, 256>>>(N);

    // CSR build
    k_scan<<<1, 1024>>>(N);
    k_fill<<<(E + 255) / 256, 256>>>(E);

    // layer 1
    k_gemm1<<<(N + 7) / 8, 256>>>(x, W1, b1, N);
    {
        long long thr = (long long)N * 32;
        k_aggregate1<<<(int)((thr + 255) / 256), 256>>>(N);
    }

    // layer 2
    k_gemm2<<<(N + 7) / 8, 256>>>(W2, b2, out, N);
    {
        long long thr = (long long)N * 32;
        k_aggregate2<<<(int)((thr + 255) / 256), 256>>>(out, N);
    }
}

// round 5
// speedup vs baseline: 1.9192x; 1.9192x over previous
#include <cuda_runtime.h>
#include <cstdint>

#define N_NODES 100000
#define IN_CH 128
#define HID 32
#define MAX_E 3400000
#define SCAN_B 1024
#define MAX_PART 128

// ---- scratch: device globals. Referenced ONLY from device code. ----
__device__ __align__(16) float g_h[N_NODES * HID];    // hs1 = h1*dinv, then hs2
__device__ __align__(16) float g_acc[N_NODES * HID];  // layer-1 accumulator
__device__ int   g_deg[N_NODES];
__device__ float g_dinv[N_NODES];
__device__ int   g_off[N_NODES + 1];
__device__ int   g_cursor[N_NODES];
__device__ int   g_csr_src[MAX_E];
__device__ int   g_part[MAX_PART];
__device__ int   g_partoff[MAX_PART];
__device__ int   g_is64;

// ---------------- dtype probe (parallel): int64 edges have all-zero high words --------
__global__ void k_detect(const int* __restrict__ ei32, int E) {
    __shared__ int nz;
    if (threadIdx.x == 0) nz = 0;
    __syncthreads();
    int n = (E > 256) ? 256 : E;
    if (threadIdx.x < n) {
        if (ei32[2 * threadIdx.x + 1] != 0) nz = 1;  // benign race
    }
    __syncthreads();
    if (threadIdx.x == 0) g_is64 = (nz == 0);
}

// ---------------- degree ----------------
__global__ void k_zero_deg(int n) {
    int i = blockIdx.x * blockDim.x + threadIdx.x;
    if (i < n) g_deg[i] = 0;
}

__global__ void k_deg(const int* __restrict__ ei32, int E) {
    int e = blockIdx.x * blockDim.x + threadIdx.x;
    if (e >= E) return;
    int d = g_is64 ? ei32[2 * (E + e)] : ei32[E + e];  // low word (LE)
    atomicAdd(&g_deg[d], 1);
}

// ---------------- scan: partial block sums ----------------
__global__ void k_partial(int n) {
    __shared__ int s[SCAN_B];
    int t = threadIdx.x;
    int i = blockIdx.x * SCAN_B + t;
    s[t] = (i < n) ? g_deg[i] : 0;
    __syncthreads();
    for (int d = SCAN_B / 2; d > 0; d >>= 1) {
        if (t < d) s[t] += s[t + d];
        __syncthreads();
    }
    if (t == 0) g_part[blockIdx.x] = s[0];
}

// ---------------- scan: partials (1 block) ----------------
__global__ void k_scanpart(int nb, int n, int E) {
    __shared__ int s[MAX_PART];
    int t = threadIdx.x;
    s[t] = (t < nb) ? g_part[t] : 0;
    __syncthreads();
    for (int d = 1; d < MAX_PART; d <<= 1) {
        int v = (t >= d) ? s[t - d] : 0;
        __syncthreads();
        s[t] += v;
        __syncthreads();
    }
    if (t < nb) g_partoff[t] = (t == 0) ? 0 : s[t - 1];
    if (t == 0) g_off[n] = E;
}

// ---------------- scan: block-local exclusive scan + dinv ----------------
__global__ void k_local(int n) {
    __shared__ int s[SCAN_B];
    int t = threadIdx.x;
    int i = blockIdx.x * SCAN_B + t;
    int deg = (i < n) ? g_deg[i] : 0;
    s[t] = deg;
    __syncthreads();
    for (int d = 1; d < SCAN_B; d <<= 1) {
        int v = (t >= d) ? s[t - d] : 0;
        __syncthreads();
        s[t] += v;
        __syncthreads();
    }
    if (i < n) {
        int excl = s[t] - deg + g_partoff[blockIdx.x];
        g_off[i] = excl;
        g_cursor[i] = excl;
        g_dinv[i] = rsqrtf((float)deg + 1.0f);  // +1 self-loop
    }
}

// ---------------- CSR fill (direct from edge_index) ----------------
__global__ void k_fill(const int* __restrict__ ei32, int E) {
    int e = blockIdx.x * blockDim.x + threadIdx.x;
    if (e >= E) return;
    int s, d;
    if (g_is64) { s = ei32[2 * e]; d = ei32[2 * (E + e)]; }
    else        { s = ei32[e];     d = ei32[E + e]; }
    int pos = atomicAdd(&g_cursor[d], 1);
    g_csr_src[pos] = s;
}

// ---------------- GEMM1: hs1 = (x@W1)*di ; acc = b1 + (x@W1)*di^2 ----------------
// 256 thr = 32 nodes x 8 col-quads; float4 accumulators; broadcast-coalesced LDS
__global__ void k_gemm1(const float* __restrict__ x,
                        const float* __restrict__ W1,
                        const float* __restrict__ b1, int n) {
    __shared__ __align__(16) float4 sW4[IN_CH * 8];   // W1[k][4q..4q+3] at [k*8+q], 16 KB
    __shared__ __align__(16) float4 sx4[32 * 32];     // 32 node rows, 16 KB
    int tid = threadIdx.x;
    int nodeBase = blockIdx.x * 32;

    for (int i = tid; i < IN_CH * 8; i += 256) sW4[i] = ((const float4*)W1)[i];
    for (int i = tid; i < 32 * 32; i += 256) {
        int nd = i >> 5, q = i & 31;
        int node = nodeBase + nd;
        sx4[i] = (node < n) ? ((const float4*)x)[(size_t)node * 32 + q]
                            : make_float4(0.f, 0.f, 0.f, 0.f);
    }
    __syncthreads();

    int nd = tid >> 3;
    int q = tid & 7;
    int node = nodeBase + nd;
    if (node >= n) return;

    float4 a = make_float4(0.f, 0.f, 0.f, 0.f);
#pragma unroll 8
    for (int k4 = 0; k4 < 32; k4++) {
        float4 xv = sx4[nd * 32 + k4];
        float4 w0 = sW4[(4 * k4 + 0) * 8 + q];
        float4 w1 = sW4[(4 * k4 + 1) * 8 + q];
        float4 w2 = sW4[(4 * k4 + 2) * 8 + q];
        float4 w3 = sW4[(4 * k4 + 3) * 8 + q];
        a.x = fmaf(xv.x, w0.x, a.x); a.y = fmaf(xv.x, w0.y, a.y);
        a.z = fmaf(xv.x, w0.z, a.z); a.w = fmaf(xv.x, w0.w, a.w);
        a.x = fmaf(xv.y, w1.x, a.x); a.y = fmaf(xv.y, w1.y, a.y);
        a.z = fmaf(xv.y, w1.z, a.z); a.w = fmaf(xv.y, w1.w, a.w);
        a.x = fmaf(xv.z, w2.x, a.x); a.y = fmaf(xv.z, w2.y, a.y);
        a.z = fmaf(xv.z, w2.z, a.z); a.w = fmaf(xv.z, w2.w, a.w);
        a.x = fmaf(xv.w, w3.x, a.x); a.y = fmaf(xv.w, w3.y, a.y);
        a.z = fmaf(xv.w, w3.z, a.z); a.w = fmaf(xv.w, w3.w, a.w);
    }
    float di = g_dinv[node];
    float4 hs = make_float4(a.x * di, a.y * di, a.z * di, a.w * di);
    ((float4*)g_h)[(size_t)node * 8 + q] = hs;
    float4 bv = ((const float4*)b1)[q];
    float4 pre = make_float4(fmaf(hs.x, di, bv.x), fmaf(hs.y, di, bv.y),
                             fmaf(hs.z, di, bv.z), fmaf(hs.w, di, bv.w));
    ((float4*)g_acc)[(size_t)node * 8 + q] = pre;
}

// ---------------- GEMM2: hs2 = (relu(acc)@W2)*di ; out = b2 + (..)*di^2 ----------------
__global__ void k_gemm2(const float* __restrict__ W2,
                        const float* __restrict__ b2,
                        float* __restrict__ out, int n) {
    __shared__ __align__(16) float4 sW4[HID * 8];     // 4 KB
    __shared__ __align__(16) float4 sa4[32 * 8];      // 4 KB
    int tid = threadIdx.x;
    int nodeBase = blockIdx.x * 32;

    for (int i = tid; i < HID * 8; i += 256) sW4[i] = ((const float4*)W2)[i];
    {
        int nd = tid >> 3, q = tid & 7;
        int node = nodeBase + nd;
        float4 v = make_float4(0.f, 0.f, 0.f, 0.f);
        if (node < n) {
            v = ((const float4*)g_acc)[(size_t)node * 8 + q];
            v.x = fmaxf(v.x, 0.f); v.y = fmaxf(v.y, 0.f);
            v.z = fmaxf(v.z, 0.f); v.w = fmaxf(v.w, 0.f);
        }
        sa4[nd * 8 + q] = v;
    }
    __syncthreads();

    int nd = tid >> 3;
    int q = tid & 7;
    int node = nodeBase + nd;
    if (node >= n) return;

    float4 a = make_float4(0.f, 0.f, 0.f, 0.f);
#pragma unroll
    for (int k4 = 0; k4 < 8; k4++) {
        float4 xv = sa4[nd * 8 + k4];
        float4 w0 = sW4[(4 * k4 + 0) * 8 + q];
        float4 w1 = sW4[(4 * k4 + 1) * 8 + q];
        float4 w2 = sW4[(4 * k4 + 2) * 8 + q];
        float4 w3 = sW4[(4 * k4 + 3) * 8 + q];
        a.x = fmaf(xv.x, w0.x, a.x); a.y = fmaf(xv.x, w0.y, a.y);
        a.z = fmaf(xv.x, w0.z, a.z); a.w = fmaf(xv.x, w0.w, a.w);
        a.x = fmaf(xv.y, w1.x, a.x); a.y = fmaf(xv.y, w1.y, a.y);
        a.z = fmaf(xv.y, w1.z, a.z); a.w = fmaf(xv.y, w1.w, a.w);
        a.x = fmaf(xv.z, w2.x, a.x); a.y = fmaf(xv.z, w2.y, a.y);
        a.z = fmaf(xv.z, w2.z, a.z); a.w = fmaf(xv.z, w2.w, a.w);
        a.x = fmaf(xv.w, w3.x, a.x); a.y = fmaf(xv.w, w3.y, a.y);
        a.z = fmaf(xv.w, w3.z, a.z); a.w = fmaf(xv.w, w3.w, a.w);
    }
    float di = g_dinv[node];
    float4 hs = make_float4(a.x * di, a.y * di, a.z * di, a.w * di);
    ((float4*)g_h)[(size_t)node * 8 + q] = hs;
    float4 bv = ((const float4*)b2)[q];
    float4 pre = make_float4(fmaf(hs.x, di, bv.x), fmaf(hs.y, di, bv.y),
                             fmaf(hs.z, di, bv.z), fmaf(hs.w, di, bv.w));
    ((float4*)out)[(size_t)node * 8 + q] = pre;
}

// ---------------- aggregation: warp per node; h pre-scaled, pure adds --------------
__device__ __forceinline__ void aggregate_node(float* __restrict__ outrow,
                                               int node, int lane) {
    int j = lane >> 3;  // edge slot 0..3
    int q = lane & 7;   // float4 lane 0..7

    int beg = g_off[node];
    int end = g_off[node + 1];

    const float4* H = (const float4*)g_h;
    float4 acc = make_float4(0.f, 0.f, 0.f, 0.f);
#pragma unroll 2
    for (int i = beg + j; i < end; i += 4) {
        int s = g_csr_src[i];
        float4 v = H[(size_t)s * 8 + q];
        acc.x += v.x; acc.y += v.y; acc.z += v.z; acc.w += v.w;
    }
#pragma unroll
    for (int m = 8; m <= 16; m <<= 1) {
        acc.x += __shfl_xor_sync(0xFFFFFFFFu, acc.x, m);
        acc.y += __shfl_xor_sync(0xFFFFFFFFu, acc.y, m);
        acc.z += __shfl_xor_sync(0xFFFFFFFFu, acc.z, m);
        acc.w += __shfl_xor_sync(0xFFFFFFFFu, acc.w, m);
    }
    if (j == 0) {
        float dd = g_dinv[node];
        float4* p = (float4*)outrow + q;
        float4 cur = *p;  // preinit (bias + self-loop)
        cur.x = fmaf(dd, acc.x, cur.x);
        cur.y = fmaf(dd, acc.y, cur.y);
        cur.z = fmaf(dd, acc.z, cur.z);
        cur.w = fmaf(dd, acc.w, cur.w);
        *p = cur;
    }
}

__global__ void k_aggregate1(int n) {
    int warp_id = (blockIdx.x * blockDim.x + threadIdx.x) >> 5;
    if (warp_id >= n) return;
    aggregate_node(g_acc + (size_t)warp_id * HID, warp_id, threadIdx.x & 31);
}

__global__ void k_aggregate2(float* __restrict__ out, int n) {
    int warp_id = (blockIdx.x * blockDim.x + threadIdx.x) >> 5;
    if (warp_id >= n) return;
    aggregate_node(out + (size_t)warp_id * HID, warp_id, threadIdx.x & 31);
}

extern "C" void kernel_launch(void* const* d_in, const int* in_sizes, int n_in,
                              void* d_out, int out_size) {
    const float* x  = (const float*)d_in[0];
    const int*   ei = (const int*)d_in[1];
    const float* W1 = (const float*)d_in[2];
    const float* b1 = (const float*)d_in[3];
    const float* W2 = (const float*)d_in[4];
    const float* b2 = (const float*)d_in[5];
    float* out = (float*)d_out;

    const int N = in_sizes[0] / IN_CH;
    const int E = in_sizes[1] / 2;
    const int nb = (N + SCAN_B - 1) / SCAN_B;

    k_detect<<<1, 256>>>(ei, E);

    k_zero_deg<<<(N + 255) / 256, 256>>>(N);
    k_deg<<<(E + 255) / 256, 256>>>(ei, E);

    k_partial<<<nb, SCAN_B>>>(N);
    k_scanpart<<<1, MAX_PART>>>(nb, N, E);
    k_local<<<nb, SCAN_B>>>(N);

    k_fill<<<(E + 255) / 256, 256>>>(ei, E);

    k_gemm1<<<(N + 31) / 32, 256>>>(x, W1, b1, N);
    {
        long long thr = (long long)N * 32;
        k_aggregate1<<<(int)((thr + 255) / 256), 256>>>(N);
    }

    k_gemm2<<<(N + 31) / 32, 256>>>(W2, b2, out, N);
    {
        long long thr = (long long)N * 32;
        k_aggregate2<<<(int)((thr + 255) / 256), 256>>>(out, N);
    }
}